// round 16
// baseline (speedup 1.0000x reference)
#include <cuda_runtime.h>
#include <cuda_fp16.h>
#include <cstdint>
#include <math.h>

#define NN 50000
#define EE 500000
#define ETOT (EE + NN)
#define CC 256
#define DD 128
#define NB_SCAN 49   // ceil(50000/1024)

#define G2_SPLIT 196                 // GEMM2 first-half tiles
#define ROW_SPLIT (G2_SPLIT * 128)   // 25088 rows/nodes

// ---------------- scratch (static __device__, no allocation) ----------------
__device__ __half g_hf16[(size_t)NN * CC];   // transformed features (fp16)
__device__ __half g_af16[(size_t)NN * CC];   // GEMM A operand (fp16)
__device__ __half g_w1f16[256 * 128];
__device__ __half g_w2f16[256 * 256];
__device__ float g_esrc[NN];
__device__ float g_edst[NN];
__device__ int   g_deg[NN];
__device__ int   g_rowptr[NN + 1];
__device__ int   g_cursor[NN];
__device__ int   g_col[ETOT];
__device__ int   g_bsum[NB_SCAN];

// ---------------- helpers ----------------
__device__ __forceinline__ uint32_t smem_u32(const void* p) {
    uint32_t a;
    asm("{ .reg .u64 t; cvta.to.shared.u64 t, %1; cvt.u32.u64 %0, t; }"
        : "=r"(a) : "l"(p));
    return a;
}

#define LDSM4(R, addr) \
    asm volatile("ldmatrix.sync.aligned.m8n8.x4.shared.b16 {%0,%1,%2,%3}, [%4];" \
                 : "=r"((R)[0]), "=r"((R)[1]), "=r"((R)[2]), "=r"((R)[3]) \
                 : "r"(addr))

#define MMA_FP16(d, a, b0, b1) \
    asm volatile("mma.sync.aligned.m16n8k16.row.col.f32.f16.f16.f32 " \
                 "{%0,%1,%2,%3},{%4,%5,%6,%7},{%8,%9},{%0,%1,%2,%3};" \
                 : "+f"((d)[0]), "+f"((d)[1]), "+f"((d)[2]), "+f"((d)[3]) \
                 : "r"((a)[0]), "r"((a)[1]), "r"((a)[2]), "r"((a)[3]), \
                   "r"(b0), "r"(b1))

#define CP16(smem_addr, gptr) \
    asm volatile("cp.async.cg.shared.global [%0], [%1], 16;" \
                 :: "r"(smem_addr), "l"(gptr))
#define CP_COMMIT() asm volatile("cp.async.commit_group;" ::: "memory")
#define CP_WAIT0()  asm volatile("cp.async.wait_group 0;" ::: "memory")

// ---------------- prep: fp16 conversions (fused) ----------------
__global__ void prep_kernel(const float* __restrict__ x,
                            const float* __restrict__ W1,
                            const float* __restrict__ W2) {
    int i = blockIdx.x * blockDim.x + threadIdx.x;
    if (i < NN * DD)    g_af16[i]  = __float2half(x[i]);
    if (i < 256 * 128)  g_w1f16[i] = __float2half(W1[i]);
    if (i < 256 * 256)  g_w2f16[i] = __float2half(W2[i]);
}

// ---------------- CSR build ----------------
__global__ void zero_deg_kernel() {
    int i = blockIdx.x * blockDim.x + threadIdx.x;
    if (i < NN) g_deg[i] = 0;
}

__global__ void count_deg_kernel(const int* __restrict__ ei) {
    int i = blockIdx.x * blockDim.x + threadIdx.x;
    if (i >= ETOT) return;
    int d = (i < EE) ? ei[EE + i] : (i - EE);
    atomicAdd(&g_deg[d], 1);
}

__global__ void scan1_kernel() {
    __shared__ int sh[1024];
    int t = threadIdx.x;
    int i = blockIdx.x * 1024 + t;
    int v = (i < NN) ? g_deg[i] : 0;
    sh[t] = v;
    __syncthreads();
    #pragma unroll
    for (int off = 1; off < 1024; off <<= 1) {
        int x = (t >= off) ? sh[t - off] : 0;
        __syncthreads();
        sh[t] += x;
        __syncthreads();
    }
    if (i < NN) g_rowptr[i + 1] = sh[t];
    if (t == 1023) g_bsum[blockIdx.x] = sh[1023];
}

__global__ void scan2_kernel() {
    __shared__ int sh[64];
    int t = threadIdx.x;
    int v = (t < NB_SCAN) ? g_bsum[t] : 0;
    sh[t] = v;
    __syncthreads();
    #pragma unroll
    for (int o = 1; o < 64; o <<= 1) {
        int x = (t >= o) ? sh[t - o] : 0;
        __syncthreads();
        sh[t] += x;
        __syncthreads();
    }
    if (t < NB_SCAN) g_bsum[t] = sh[t] - v;   // exclusive
}

__global__ void scan3_kernel() {
    int t = threadIdx.x;
    int i = blockIdx.x * 1024 + t;
    if (i < NN) {
        int r = g_rowptr[i + 1] + g_bsum[blockIdx.x];
        g_rowptr[i + 1] = r;
        if (i + 1 < NN) g_cursor[i + 1] = r;
        if (i == 0) { g_rowptr[0] = 0; g_cursor[0] = 0; }
    }
}

__global__ void fill_kernel(const int* __restrict__ ei) {
    int i = blockIdx.x * blockDim.x + threadIdx.x;
    if (i >= ETOT) return;
    int s, d;
    if (i < EE) { s = ei[i]; d = ei[EE + i]; }
    else        { s = i - EE; d = s; }
    int pos = atomicAdd(&g_cursor[d], 1);
    g_col[pos] = s;
}

// ---------------- HMMA GEMM (fp16, 128x256 full-N) + fused dots ----------------
#define SST 40                       // smem row stride (fp16), conflict-free
#define ABYTES (128 * SST * 2)       // 10240
#define BBYTES (256 * SST * 2)       // 20480
#define STAGE_B (ABYTES + BBYTES)    // 30720
#define SM_TOTAL (2 * STAGE_B)       // 61440

template <int K, int LAYER>
__global__ __launch_bounds__(256) void mma_gemm_kernel(const float* __restrict__ a_src,
                                                       const float* __restrict__ a_dst,
                                                       int bmoff) {
    extern __shared__ __align__(16) char dsm[];
    __shared__ float sas[256], sad[256], sds[128], sdd[128];

    const __half* __restrict__ Af = g_af16;
    const __half* __restrict__ Wf = (LAYER == 1) ? g_w1f16 : g_w2f16;

    int tid = threadIdx.x;
    int wid = tid >> 5;
    int lane = tid & 31;
    int bm = (blockIdx.x + bmoff) * 128;
    int wm = (wid & 1) * 64;
    int wn = (wid >> 1) * 64;

    uint32_t sbase = smem_u32(dsm);

    if (tid < 256) {
        sas[tid] = a_src[tid];
        sad[tid] = a_dst[tid];
    }
    if (tid < 128) { sds[tid] = 0.f; sdd[tid] = 0.f; }

    float acc[4][8][4];
    #pragma unroll
    for (int a = 0; a < 4; a++)
        #pragma unroll
        for (int b = 0; b < 8; b++)
            #pragma unroll
            for (int c = 0; c < 4; c++) acc[a][b][c] = 0.f;

    const int nchunk = K >> 5;

    auto load_chunk = [&](int c, int st) {
        int k0 = c * 32;
        uint32_t sA = sbase + st * STAGE_B;
        uint32_t sB = sA + ABYTES;
        #pragma unroll
        for (int it = 0; it < 2; it++) {
            int idx = tid + it * 256;
            int r = idx >> 2;
            int q = (idx & 3) << 3;
            int row = bm + r;
            if (row > NN - 1) row = NN - 1;
            CP16(sA + (uint32_t)(r * SST + q) * 2, &Af[(size_t)row * K + k0 + q]);
        }
        #pragma unroll
        for (int it = 0; it < 4; it++) {
            int idx = tid + it * 256;
            int r = idx >> 2;
            int q = (idx & 3) << 3;
            CP16(sB + (uint32_t)(r * SST + q) * 2, &Wf[(size_t)r * K + k0 + q]);
        }
    };

    int a_row = wm + (lane & 15);
    int a_k8  = (lane >> 4) << 3;
    int b_row = wn + (lane & 7) + ((lane >> 4) << 3);
    int b_k8  = ((lane >> 3) & 1) << 3;

    load_chunk(0, 0);
    CP_COMMIT();

    for (int c = 0; c < nchunk; c++) {
        int st = c & 1;
        CP_WAIT0();
        __syncthreads();
        if (c + 1 < nchunk) {
            load_chunk(c + 1, (c + 1) & 1);
            CP_COMMIT();
        }

        uint32_t sA = sbase + st * STAGE_B;
        uint32_t sB = sA + ABYTES;

        #pragma unroll
        for (int ks = 0; ks < 2; ks++) {
            int kk = ks * 16;
            uint32_t aF[4][4];
            #pragma unroll
            for (int mt = 0; mt < 4; mt++) {
                uint32_t off = (uint32_t)(((a_row + mt * 16) * SST + kk + a_k8) * 2);
                LDSM4(aF[mt], sA + off);
            }
            uint32_t bF[4][4];
            #pragma unroll
            for (int bt = 0; bt < 4; bt++) {
                uint32_t off = (uint32_t)(((b_row + bt * 16) * SST + kk + b_k8) * 2);
                LDSM4(bF[bt], sB + off);
            }
            #pragma unroll
            for (int mt = 0; mt < 4; mt++) {
                #pragma unroll
                for (int nt = 0; nt < 8; nt++) {
                    int bt = nt >> 1;
                    int sbi = (nt & 1) * 2;
                    MMA_FP16(acc[mt][nt], aF[mt], bF[bt][sbi], bF[bt][sbi + 1]);
                }
            }
        }
        __syncthreads();
    }

    // ---- epilogue: fp16 h store + complete fused dots ----
    int gid = lane >> 2;
    int tig = lane & 3;
    #pragma unroll
    for (int mt = 0; mt < 4; mt++) {
        float ds0 = 0.f, ds1 = 0.f, dd0 = 0.f, dd1 = 0.f;
        #pragma unroll
        for (int nt = 0; nt < 8; nt++) {
            int col = wn + nt * 8 + tig * 2;
            int row0 = bm + wm + mt * 16 + gid;
            if (row0 < NN)
                *(__half2*)&g_hf16[(size_t)row0 * CC + col] =
                    __floats2half2_rn(acc[mt][nt][0], acc[mt][nt][1]);
            int row1 = row0 + 8;
            if (row1 < NN)
                *(__half2*)&g_hf16[(size_t)row1 * CC + col] =
                    __floats2half2_rn(acc[mt][nt][2], acc[mt][nt][3]);
            float as0 = sas[col], as1 = sas[col + 1];
            float ad0 = sad[col], ad1 = sad[col + 1];
            ds0 += acc[mt][nt][0] * as0 + acc[mt][nt][1] * as1;
            dd0 += acc[mt][nt][0] * ad0 + acc[mt][nt][1] * ad1;
            ds1 += acc[mt][nt][2] * as0 + acc[mt][nt][3] * as1;
            dd1 += acc[mt][nt][2] * ad0 + acc[mt][nt][3] * ad1;
        }
        #pragma unroll
        for (int o = 1; o <= 2; o <<= 1) {
            ds0 += __shfl_xor_sync(0xFFFFFFFFu, ds0, o);
            ds1 += __shfl_xor_sync(0xFFFFFFFFu, ds1, o);
            dd0 += __shfl_xor_sync(0xFFFFFFFFu, dd0, o);
            dd1 += __shfl_xor_sync(0xFFFFFFFFu, dd1, o);
        }
        if (tig == 0) {
            int lr = wm + mt * 16 + gid;
            atomicAdd(&sds[lr], ds0);
            atomicAdd(&sdd[lr], dd0);
            atomicAdd(&sds[lr + 8], ds1);
            atomicAdd(&sdd[lr + 8], dd1);
        }
    }
    __syncthreads();
    if (tid < 128) {
        int row = bm + tid;
        if (row < NN) {
            g_esrc[row] = sds[tid];
            g_edst[row] = sdd[tid];
        }
    }
}

// ---------------- softmax + aggregate: 2 warps/node, 4-edge unroll, node range ----
template <bool FIRST>
__global__ void aggregate_kernel(const float* __restrict__ bias,
                                 float* __restrict__ out,
                                 int wbase, int wlimit) {
    int gw = (blockIdx.x * blockDim.x + threadIdx.x) >> 5;
    int w = wbase + (gw >> 1);     // node
    int hf = gw & 1;               // channel half
    if (w >= wlimit) return;
    int lane = threadIdx.x & 31;
    int c0 = hf * 128 + lane * 4;  // 4 channels per lane

    float edst = g_edst[w];
    int beg = g_rowptr[w];
    int end = g_rowptr[w + 1];

    float sum = 0.f;
    float acc0 = 0.f, acc1 = 0.f, acc2 = 0.f, acc3 = 0.f;

    auto consume = [&](float e, uint2 u) {
        float ea = e + edst;
        ea = ea > 0.f ? ea : 0.2f * ea;
        float p = __expf(ea);
        sum += p;
        float2 f0 = __half22float2(*(__half2*)&u.x);
        float2 f1 = __half22float2(*(__half2*)&u.y);
        acc0 += p * f0.x; acc1 += p * f0.y;
        acc2 += p * f1.x; acc3 += p * f1.y;
    };

    int j = beg;
    for (; j + 3 < end; j += 4) {
        int s0 = g_col[j];
        int s1 = g_col[j + 1];
        int s2 = g_col[j + 2];
        int s3 = g_col[j + 3];
        float e0 = g_esrc[s0];
        float e1 = g_esrc[s1];
        float e2 = g_esrc[s2];
        float e3 = g_esrc[s3];
        uint2 u0 = *(const uint2*)&g_hf16[(size_t)s0 * CC + c0];
        uint2 u1 = *(const uint2*)&g_hf16[(size_t)s1 * CC + c0];
        uint2 u2 = *(const uint2*)&g_hf16[(size_t)s2 * CC + c0];
        uint2 u3 = *(const uint2*)&g_hf16[(size_t)s3 * CC + c0];
        consume(e0, u0);
        consume(e1, u1);
        consume(e2, u2);
        consume(e3, u3);
    }
    for (; j < end; j++) {
        int s0 = g_col[j];
        float e0 = g_esrc[s0];
        uint2 u0 = *(const uint2*)&g_hf16[(size_t)s0 * CC + c0];
        consume(e0, u0);
    }

    float inv = 1.f / (sum + 1e-16f);
    float v0 = fmaxf(acc0 * inv + bias[c0 + 0], 0.f);
    float v1 = fmaxf(acc1 * inv + bias[c0 + 1], 0.f);
    float v2 = fmaxf(acc2 * inv + bias[c0 + 2], 0.f);
    float v3 = fmaxf(acc3 * inv + bias[c0 + 3], 0.f);

    float* dst = &out[(size_t)w * 512 + (FIRST ? 0 : 256) + c0];
    *(float4*)dst = make_float4(v0, v1, v2, v3);
    if (FIRST) {
        *(__half2*)&g_af16[(size_t)w * CC + c0] = __floats2half2_rn(v0, v1);
        *(__half2*)&g_af16[(size_t)w * CC + c0 + 2] = __floats2half2_rn(v2, v3);
    }
}

// ---------------- launch ----------------
extern "C" void kernel_launch(void* const* d_in, const int* in_sizes, int n_in,
                              void* d_out, int out_size) {
    const float* x    = (const float*)d_in[0];
    const int*   ei   = (const int*)d_in[1];
    const float* W1   = (const float*)d_in[2];
    const float* a1s  = (const float*)d_in[3];
    const float* a1d  = (const float*)d_in[4];
    const float* b1   = (const float*)d_in[5];
    const float* W2   = (const float*)d_in[6];
    const float* a2s  = (const float*)d_in[7];
    const float* a2d  = (const float*)d_in[8];
    const float* b2   = (const float*)d_in[9];
    float* out = (float*)d_out;

    static cudaStream_t strB = nullptr;
    static cudaEvent_t evFork = nullptr, evJoin = nullptr;
    static cudaEvent_t evA = nullptr, evB = nullptr, evG2 = nullptr;
    if (!strB) {
        cudaStreamCreateWithFlags(&strB, cudaStreamNonBlocking);
        cudaEventCreateWithFlags(&evFork, cudaEventDisableTiming);
        cudaEventCreateWithFlags(&evJoin, cudaEventDisableTiming);
        cudaEventCreateWithFlags(&evA, cudaEventDisableTiming);
        cudaEventCreateWithFlags(&evB, cudaEventDisableTiming);
        cudaEventCreateWithFlags(&evG2, cudaEventDisableTiming);
        cudaFuncSetAttribute(mma_gemm_kernel<128, 1>,
                             cudaFuncAttributeMaxDynamicSharedMemorySize, SM_TOTAL);
        cudaFuncSetAttribute(mma_gemm_kernel<256, 2>,
                             cudaFuncAttributeMaxDynamicSharedMemorySize, SM_TOTAL);
    }
    cudaStream_t s0 = (cudaStream_t)0;

    const int ntiles = (NN + 127) / 128;        // 391
    const int g2a = G2_SPLIT;                   // 196
    const int g2b = ntiles - G2_SPLIT;          // 195
    const int agg1a_blocks = (ROW_SPLIT * 2 + 7) / 8;
    const int agg1b_blocks = ((NN - ROW_SPLIT) * 2 + 7) / 8;
    const int agg_blocks   = (NN * 2 + 7) / 8;

    // Submission order keeps mma_gemm_kernel<128,1> at index 3 (ncu profiles #3).
    cudaEventRecord(evFork, s0);
    cudaStreamWaitEvent(strB, evFork, 0);

    prep_kernel<<<(NN * DD + 255) / 256, 256, 0, s0>>>(x, W1, W2);            // 0
    zero_deg_kernel<<<(NN + 255) / 256, 256, 0, strB>>>();                    // 1
    count_deg_kernel<<<(ETOT + 255) / 256, 256, 0, strB>>>(ei);               // 2
    mma_gemm_kernel<128, 1><<<ntiles, 256, SM_TOTAL, s0>>>(a1s, a1d, 0);      // 3
    scan1_kernel<<<NB_SCAN, 1024, 0, strB>>>();                               // 4
    scan2_kernel<<<1, 64, 0, strB>>>();                                       // 5
    scan3_kernel<<<NB_SCAN, 1024, 0, strB>>>();                               // 6
    fill_kernel<<<(ETOT + 255) / 256, 256, 0, strB>>>(ei);                    // 7
    cudaEventRecord(evJoin, strB);

    // agg1 split into node halves on s0; GEMM2 halves pipeline on strB
    cudaStreamWaitEvent(s0, evJoin, 0);
    aggregate_kernel<true><<<agg1a_blocks, 256, 0, s0>>>(b1, out, 0, ROW_SPLIT);      // 8
    cudaEventRecord(evA, s0);
    aggregate_kernel<true><<<agg1b_blocks, 256, 0, s0>>>(b1, out, ROW_SPLIT, NN);     // 9
    cudaEventRecord(evB, s0);

    cudaStreamWaitEvent(strB, evA, 0);
    mma_gemm_kernel<256, 2><<<g2a, 256, SM_TOTAL, strB>>>(a2s, a2d, 0);               // 10
    cudaStreamWaitEvent(strB, evB, 0);
    mma_gemm_kernel<256, 2><<<g2b, 256, SM_TOTAL, strB>>>(a2s, a2d, G2_SPLIT);        // 11
    cudaEventRecord(evG2, strB);

    cudaStreamWaitEvent(s0, evG2, 0);
    aggregate_kernel<false><<<agg_blocks, 256, 0, s0>>>(b2, out, 0, NN);              // 12
}

// round 17
// speedup vs baseline: 1.1105x; 1.1105x over previous
#include <cuda_runtime.h>
#include <cuda_fp16.h>
#include <cstdint>
#include <math.h>

#define NN 50000
#define EE 500000
#define ETOT (EE + NN)
#define CC 256
#define DD 128
#define NB_SCAN 49   // ceil(50000/1024)

// ---------------- scratch (static __device__, no allocation) ----------------
__device__ __half g_hf16[(size_t)NN * CC];   // transformed features (fp16)
__device__ __half g_af16[(size_t)NN * CC];   // x1 fp16 (layer-2 GEMM A operand)
__device__ __half g_w1f16[256 * 128];
__device__ __half g_w2f16[256 * 256];
__device__ float g_esrc[NN];
__device__ float g_edst[NN];
__device__ int   g_deg[NN];
__device__ int   g_rowptr[NN + 1];
__device__ int   g_cursor[NN];
__device__ int   g_col[ETOT];
__device__ int   g_bsum[NB_SCAN];

// ---------------- helpers ----------------
__device__ __forceinline__ uint32_t smem_u32(const void* p) {
    uint32_t a;
    asm("{ .reg .u64 t; cvta.to.shared.u64 t, %1; cvt.u32.u64 %0, t; }"
        : "=r"(a) : "l"(p));
    return a;
}

#define LDSM4(R, addr) \
    asm volatile("ldmatrix.sync.aligned.m8n8.x4.shared.b16 {%0,%1,%2,%3}, [%4];" \
                 : "=r"((R)[0]), "=r"((R)[1]), "=r"((R)[2]), "=r"((R)[3]) \
                 : "r"(addr))

#define MMA_FP16(d, a, b0, b1) \
    asm volatile("mma.sync.aligned.m16n8k16.row.col.f32.f16.f16.f32 " \
                 "{%0,%1,%2,%3},{%4,%5,%6,%7},{%8,%9},{%0,%1,%2,%3};" \
                 : "+f"((d)[0]), "+f"((d)[1]), "+f"((d)[2]), "+f"((d)[3]) \
                 : "r"((a)[0]), "r"((a)[1]), "r"((a)[2]), "r"((a)[3]), \
                   "r"(b0), "r"(b1))

#define CP16(smem_addr, gptr) \
    asm volatile("cp.async.cg.shared.global [%0], [%1], 16;" \
                 :: "r"(smem_addr), "l"(gptr))
#define CP_COMMIT() asm volatile("cp.async.commit_group;" ::: "memory")
#define CP_WAIT0()  asm volatile("cp.async.wait_group 0;" ::: "memory")

// ---------------- prep: W conversions only (x handled in GEMM1) ----------------
__global__ void prep_kernel(const float* __restrict__ W1,
                            const float* __restrict__ W2) {
    int i = blockIdx.x * blockDim.x + threadIdx.x;
    if (i < 256 * 128)  g_w1f16[i] = __float2half(W1[i]);
    if (i < 256 * 256)  g_w2f16[i] = __float2half(W2[i]);
}

// ---------------- CSR build ----------------
__global__ void zero_deg_kernel() {
    int i = blockIdx.x * blockDim.x + threadIdx.x;
    if (i < NN) g_deg[i] = 0;
}

__global__ void count_deg_kernel(const int* __restrict__ ei) {
    int i = blockIdx.x * blockDim.x + threadIdx.x;
    if (i >= ETOT) return;
    int d = (i < EE) ? ei[EE + i] : (i - EE);
    atomicAdd(&g_deg[d], 1);
}

__global__ void scan1_kernel() {
    __shared__ int sh[1024];
    int t = threadIdx.x;
    int i = blockIdx.x * 1024 + t;
    int v = (i < NN) ? g_deg[i] : 0;
    sh[t] = v;
    __syncthreads();
    #pragma unroll
    for (int off = 1; off < 1024; off <<= 1) {
        int x = (t >= off) ? sh[t - off] : 0;
        __syncthreads();
        sh[t] += x;
        __syncthreads();
    }
    if (i < NN) g_rowptr[i + 1] = sh[t];
    if (t == 1023) g_bsum[blockIdx.x] = sh[1023];
}

__global__ void scan2_kernel() {
    __shared__ int sh[64];
    int t = threadIdx.x;
    int v = (t < NB_SCAN) ? g_bsum[t] : 0;
    sh[t] = v;
    __syncthreads();
    #pragma unroll
    for (int o = 1; o < 64; o <<= 1) {
        int x = (t >= o) ? sh[t - o] : 0;
        __syncthreads();
        sh[t] += x;
        __syncthreads();
    }
    if (t < NB_SCAN) g_bsum[t] = sh[t] - v;   // exclusive
}

__global__ void scan3_kernel() {
    int t = threadIdx.x;
    int i = blockIdx.x * 1024 + t;
    if (i < NN) {
        int r = g_rowptr[i + 1] + g_bsum[blockIdx.x];
        g_rowptr[i + 1] = r;
        if (i + 1 < NN) g_cursor[i + 1] = r;
        if (i == 0) { g_rowptr[0] = 0; g_cursor[0] = 0; }
    }
}

__global__ void fill_kernel(const int* __restrict__ ei) {
    int i = blockIdx.x * blockDim.x + threadIdx.x;
    if (i >= ETOT) return;
    int s, d;
    if (i < EE) { s = ei[i]; d = ei[EE + i]; }
    else        { s = i - EE; d = s; }
    int pos = atomicAdd(&g_cursor[d], 1);
    g_col[pos] = s;
}

// ---------------- HMMA GEMM (fp16, 128x256 full-N) + fused dots ----------------
// LAYER 1: A loaded from fp32 x with in-kernel fp16 conversion (LDG+STS).
// LAYER 2: A loaded fp16 via cp.async from g_af16. B always cp.async.
#define SST 40                       // smem row stride (fp16), conflict-free
#define ABYTES (128 * SST * 2)       // 10240
#define BBYTES (256 * SST * 2)       // 20480
#define STAGE_B (ABYTES + BBYTES)    // 30720
#define SM_TOTAL (2 * STAGE_B)       // 61440

template <int K, int LAYER>
__global__ __launch_bounds__(256) void mma_gemm_kernel(const float* __restrict__ xf32,
                                                       const float* __restrict__ a_src,
                                                       const float* __restrict__ a_dst) {
    extern __shared__ __align__(16) char dsm[];
    __shared__ float sas[256], sad[256], sds[128], sdd[128];

    const __half* __restrict__ Af = g_af16;
    const __half* __restrict__ Wf = (LAYER == 1) ? g_w1f16 : g_w2f16;

    int tid = threadIdx.x;
    int wid = tid >> 5;
    int lane = tid & 31;
    int bm = blockIdx.x * 128;
    int wm = (wid & 1) * 64;
    int wn = (wid >> 1) * 64;

    uint32_t sbase = smem_u32(dsm);

    if (tid < 256) {
        sas[tid] = a_src[tid];
        sad[tid] = a_dst[tid];
    }
    if (tid < 128) { sds[tid] = 0.f; sdd[tid] = 0.f; }

    float acc[4][8][4];
    #pragma unroll
    for (int a = 0; a < 4; a++)
        #pragma unroll
        for (int b = 0; b < 8; b++)
            #pragma unroll
            for (int c = 0; c < 4; c++) acc[a][b][c] = 0.f;

    const int nchunk = K >> 5;

    // B tile via cp.async (both layers)
    auto load_chunk_b = [&](int c, int st) {
        int k0 = c * 32;
        uint32_t sB = sbase + st * STAGE_B + ABYTES;
        #pragma unroll
        for (int it = 0; it < 4; it++) {
            int idx = tid + it * 256;
            int r = idx >> 2;
            int q = (idx & 3) << 3;
            CP16(sB + (uint32_t)(r * SST + q) * 2, &Wf[(size_t)r * K + k0 + q]);
        }
    };
    // A tile: LAYER1 from fp32 x (LDG+convert+STS); LAYER2 via cp.async
    auto load_chunk_a = [&](int c, int st) {
        int k0 = c * 32;
        uint32_t sA = sbase + st * STAGE_B;
        #pragma unroll
        for (int it = 0; it < 2; it++) {
            int idx = tid + it * 256;
            int r = idx >> 2;
            int q = (idx & 3) << 3;
            int row = bm + r;
            if (row > NN - 1) row = NN - 1;
            if (LAYER == 1) {
                const float4* p = (const float4*)&xf32[(size_t)row * K + k0 + q];
                float4 v0 = p[0], v1 = p[1];
                __half2 h0 = __floats2half2_rn(v0.x, v0.y);
                __half2 h1 = __floats2half2_rn(v0.z, v0.w);
                __half2 h2 = __floats2half2_rn(v1.x, v1.y);
                __half2 h3 = __floats2half2_rn(v1.z, v1.w);
                uint4 pk = make_uint4(*(uint32_t*)&h0, *(uint32_t*)&h1,
                                      *(uint32_t*)&h2, *(uint32_t*)&h3);
                *(uint4*)(dsm + st * STAGE_B + (r * SST + q) * 2) = pk;
            } else {
                CP16(sA + (uint32_t)(r * SST + q) * 2, &Af[(size_t)row * K + k0 + q]);
            }
        }
    };

    int a_row = wm + (lane & 15);
    int a_k8  = (lane >> 4) << 3;
    int b_row = wn + (lane & 7) + ((lane >> 4) << 3);
    int b_k8  = ((lane >> 3) & 1) << 3;

    load_chunk_b(0, 0);
    load_chunk_a(0, 0);
    CP_COMMIT();

    for (int c = 0; c < nchunk; c++) {
        int st = c & 1;
        CP_WAIT0();
        __syncthreads();
        if (c + 1 < nchunk) {
            load_chunk_b(c + 1, (c + 1) & 1);
            load_chunk_a(c + 1, (c + 1) & 1);
            CP_COMMIT();
        }

        uint32_t sA = sbase + st * STAGE_B;
        uint32_t sB = sA + ABYTES;

        #pragma unroll
        for (int ks = 0; ks < 2; ks++) {
            int kk = ks * 16;
            uint32_t aF[4][4];
            #pragma unroll
            for (int mt = 0; mt < 4; mt++) {
                uint32_t off = (uint32_t)(((a_row + mt * 16) * SST + kk + a_k8) * 2);
                LDSM4(aF[mt], sA + off);
            }
            uint32_t bF[4][4];
            #pragma unroll
            for (int bt = 0; bt < 4; bt++) {
                uint32_t off = (uint32_t)(((b_row + bt * 16) * SST + kk + b_k8) * 2);
                LDSM4(bF[bt], sB + off);
            }
            #pragma unroll
            for (int mt = 0; mt < 4; mt++) {
                #pragma unroll
                for (int nt = 0; nt < 8; nt++) {
                    int bt = nt >> 1;
                    int sbi = (nt & 1) * 2;
                    MMA_FP16(acc[mt][nt], aF[mt], bF[bt][sbi], bF[bt][sbi + 1]);
                }
            }
        }
        __syncthreads();
    }

    // ---- epilogue: fp16 h store + complete fused dots ----
    int gid = lane >> 2;
    int tig = lane & 3;
    #pragma unroll
    for (int mt = 0; mt < 4; mt++) {
        float ds0 = 0.f, ds1 = 0.f, dd0 = 0.f, dd1 = 0.f;
        #pragma unroll
        for (int nt = 0; nt < 8; nt++) {
            int col = wn + nt * 8 + tig * 2;
            int row0 = bm + wm + mt * 16 + gid;
            if (row0 < NN)
                *(__half2*)&g_hf16[(size_t)row0 * CC + col] =
                    __floats2half2_rn(acc[mt][nt][0], acc[mt][nt][1]);
            int row1 = row0 + 8;
            if (row1 < NN)
                *(__half2*)&g_hf16[(size_t)row1 * CC + col] =
                    __floats2half2_rn(acc[mt][nt][2], acc[mt][nt][3]);
            float as0 = sas[col], as1 = sas[col + 1];
            float ad0 = sad[col], ad1 = sad[col + 1];
            ds0 += acc[mt][nt][0] * as0 + acc[mt][nt][1] * as1;
            dd0 += acc[mt][nt][0] * ad0 + acc[mt][nt][1] * ad1;
            ds1 += acc[mt][nt][2] * as0 + acc[mt][nt][3] * as1;
            dd1 += acc[mt][nt][2] * ad0 + acc[mt][nt][3] * ad1;
        }
        #pragma unroll
        for (int o = 1; o <= 2; o <<= 1) {
            ds0 += __shfl_xor_sync(0xFFFFFFFFu, ds0, o);
            ds1 += __shfl_xor_sync(0xFFFFFFFFu, ds1, o);
            dd0 += __shfl_xor_sync(0xFFFFFFFFu, dd0, o);
            dd1 += __shfl_xor_sync(0xFFFFFFFFu, dd1, o);
        }
        if (tig == 0) {
            int lr = wm + mt * 16 + gid;
            atomicAdd(&sds[lr], ds0);
            atomicAdd(&sdd[lr], dd0);
            atomicAdd(&sds[lr + 8], ds1);
            atomicAdd(&sdd[lr + 8], dd1);
        }
    }
    __syncthreads();
    if (tid < 128) {
        int row = bm + tid;
        if (row < NN) {
            g_esrc[row] = sds[tid];
            g_edst[row] = sdd[tid];
        }
    }
}

// ---------------- softmax + aggregate: 2 warps/node, 4-edge unroll ----------------
template <bool FIRST>
__global__ void aggregate_kernel(const float* __restrict__ bias,
                                 float* __restrict__ out) {
    int gw = (blockIdx.x * blockDim.x + threadIdx.x) >> 5;
    int w = gw >> 1;           // node
    int hf = gw & 1;           // channel half
    if (w >= NN) return;
    int lane = threadIdx.x & 31;
    int c0 = hf * 128 + lane * 4;   // 4 channels per lane

    float edst = g_edst[w];
    int beg = g_rowptr[w];
    int end = g_rowptr[w + 1];

    float sum = 0.f;
    float acc0 = 0.f, acc1 = 0.f, acc2 = 0.f, acc3 = 0.f;

    auto consume = [&](float e, uint2 u) {
        float ea = e + edst;
        ea = ea > 0.f ? ea : 0.2f * ea;
        float p = __expf(ea);
        sum += p;
        float2 f0 = __half22float2(*(__half2*)&u.x);
        float2 f1 = __half22float2(*(__half2*)&u.y);
        acc0 += p * f0.x; acc1 += p * f0.y;
        acc2 += p * f1.x; acc3 += p * f1.y;
    };

    int j = beg;
    for (; j + 3 < end; j += 4) {
        int s0 = g_col[j];
        int s1 = g_col[j + 1];
        int s2 = g_col[j + 2];
        int s3 = g_col[j + 3];
        float e0 = g_esrc[s0];
        float e1 = g_esrc[s1];
        float e2 = g_esrc[s2];
        float e3 = g_esrc[s3];
        uint2 u0 = *(const uint2*)&g_hf16[(size_t)s0 * CC + c0];
        uint2 u1 = *(const uint2*)&g_hf16[(size_t)s1 * CC + c0];
        uint2 u2 = *(const uint2*)&g_hf16[(size_t)s2 * CC + c0];
        uint2 u3 = *(const uint2*)&g_hf16[(size_t)s3 * CC + c0];
        consume(e0, u0);
        consume(e1, u1);
        consume(e2, u2);
        consume(e3, u3);
    }
    for (; j < end; j++) {
        int s0 = g_col[j];
        float e0 = g_esrc[s0];
        uint2 u0 = *(const uint2*)&g_hf16[(size_t)s0 * CC + c0];
        consume(e0, u0);
    }

    float inv = 1.f / (sum + 1e-16f);
    float v0 = fmaxf(acc0 * inv + bias[c0 + 0], 0.f);
    float v1 = fmaxf(acc1 * inv + bias[c0 + 1], 0.f);
    float v2 = fmaxf(acc2 * inv + bias[c0 + 2], 0.f);
    float v3 = fmaxf(acc3 * inv + bias[c0 + 3], 0.f);

    float* dst = &out[(size_t)w * 512 + (FIRST ? 0 : 256) + c0];
    *(float4*)dst = make_float4(v0, v1, v2, v3);
    if (FIRST) {
        *(__half2*)&g_af16[(size_t)w * CC + c0] = __floats2half2_rn(v0, v1);
        *(__half2*)&g_af16[(size_t)w * CC + c0 + 2] = __floats2half2_rn(v2, v3);
    }
}

// ---------------- launch ----------------
extern "C" void kernel_launch(void* const* d_in, const int* in_sizes, int n_in,
                              void* d_out, int out_size) {
    const float* x    = (const float*)d_in[0];
    const int*   ei   = (const int*)d_in[1];
    const float* W1   = (const float*)d_in[2];
    const float* a1s  = (const float*)d_in[3];
    const float* a1d  = (const float*)d_in[4];
    const float* b1   = (const float*)d_in[5];
    const float* W2   = (const float*)d_in[6];
    const float* a2s  = (const float*)d_in[7];
    const float* a2d  = (const float*)d_in[8];
    const float* b2   = (const float*)d_in[9];
    float* out = (float*)d_out;

    static cudaStream_t strB = nullptr;
    static cudaEvent_t evFork = nullptr, evJoin = nullptr;
    if (!strB) {
        cudaStreamCreateWithFlags(&strB, cudaStreamNonBlocking);
        cudaEventCreateWithFlags(&evFork, cudaEventDisableTiming);
        cudaEventCreateWithFlags(&evJoin, cudaEventDisableTiming);
        cudaFuncSetAttribute(mma_gemm_kernel<128, 1>,
                             cudaFuncAttributeMaxDynamicSharedMemorySize, SM_TOTAL);
        cudaFuncSetAttribute(mma_gemm_kernel<256, 2>,
                             cudaFuncAttributeMaxDynamicSharedMemorySize, SM_TOTAL);
    }
    cudaStream_t s0 = (cudaStream_t)0;

    dim3 ggrid((NN + 127) / 128, 1);
    int agg_blocks = (NN * 2 + 7) / 8;    // 2 warps per node, 8 warps/block

    // Submission order keeps mma_gemm_kernel<128,1> at index 3 (ncu profiles #3).
    cudaEventRecord(evFork, s0);
    cudaStreamWaitEvent(strB, evFork, 0);

    prep_kernel<<<(256 * 256 + 255) / 256, 256, 0, s0>>>(W1, W2);           // 0
    zero_deg_kernel<<<(NN + 255) / 256, 256, 0, strB>>>();                  // 1
    count_deg_kernel<<<(ETOT + 255) / 256, 256, 0, strB>>>(ei);             // 2
    mma_gemm_kernel<128, 1><<<ggrid, 256, SM_TOTAL, s0>>>(x, a1s, a1d);     // 3
    scan1_kernel<<<NB_SCAN, 1024, 0, strB>>>();                             // 4
    scan2_kernel<<<1, 64, 0, strB>>>();                                     // 5
    scan3_kernel<<<NB_SCAN, 1024, 0, strB>>>();                             // 6
    fill_kernel<<<(ETOT + 255) / 256, 256, 0, strB>>>(ei);                  // 7
    cudaEventRecord(evJoin, strB);

    cudaStreamWaitEvent(s0, evJoin, 0);
    aggregate_kernel<true><<<agg_blocks, 256, 0, s0>>>(b1, out);            // 8

    mma_gemm_kernel<256, 2><<<ggrid, 256, SM_TOTAL, s0>>>(x, a2s, a2d);     // 9
    aggregate_kernel<false><<<agg_blocks, 256, 0, s0>>>(b2, out);           // 10
}